// round 8
// baseline (speedup 1.0000x reference)
#include <cuda_runtime.h>
#include <cuda_fp16.h>
#include <cstdint>

// CodeBook VQ argmin: 1-pass fp16 tensor-core screen + exact fp32 candidate rescue.
//   d_hi[m][k] = e2[k] - 2*(Xhi·Ehi^T)   (one HMMA pass, error std ~6.4e-3)
//   candidates = { k : d_hi <= running_min + DELTA }  (no-miss: running_min >= final_min)
//   exact rescore of candidates with x~ = fp32(xh)+fp32(xl) (err 2^-22) vs fp32 emb.

#define NCODES 1024
#define KDIM   256
#define NPIX   4096
#define MCTA   128
#define DELTA  0.25f
#define LCAP   16

#define ASTR   264              // A smem row stride in halves (528B)
#define BSTR   72               // B smem row stride in halves (144B)
#define BK     64
#define KT     4                // 4 x 64 = K 256, hi pass only

#define AHI_OFF   0             // 128*528 = 67584
#define ALO_OFF   67584         // rescue only
#define B0_OFF    135168        // 18432
#define B1_OFF    153600
#define E2_OFF    172032        // 4096
#define MK_OFF    176128        // 128*8
#define CNT_OFF   177152        // 128*4
#define LST_OFF   177664        // 128*16*4
#define SMEM_SZ   185856

__device__ __align__(16) __half g_Ehi[NCODES * KDIM];
__device__ float g_e2[NCODES];

__device__ __forceinline__ void ldmx4(uint32_t* r, uint32_t addr) {
    asm volatile("ldmatrix.sync.aligned.m8n8.x4.shared.b16 {%0,%1,%2,%3}, [%4];"
                 : "=r"(r[0]), "=r"(r[1]), "=r"(r[2]), "=r"(r[3]) : "r"(addr));
}
__device__ __forceinline__ void mma16816(float* c, const uint32_t* a, uint32_t b0, uint32_t b1) {
    asm volatile("mma.sync.aligned.m16n8k16.row.col.f32.f16.f16.f32 "
                 "{%0,%1,%2,%3}, {%4,%5,%6,%7}, {%8,%9}, {%0,%1,%2,%3};"
                 : "+f"(c[0]), "+f"(c[1]), "+f"(c[2]), "+f"(c[3])
                 : "r"(a[0]), "r"(a[1]), "r"(a[2]), "r"(a[3]), "r"(b0), "r"(b1));
}
__device__ __forceinline__ void cp16(uint32_t dst, const void* src) {
    asm volatile("cp.async.cg.shared.global [%0], [%1], 16;"
                 :: "r"(dst), "l"(__cvta_generic_to_global(src)) : "memory");
}
#define CP_COMMIT() asm volatile("cp.async.commit_group;" ::: "memory")
#define CP_WAIT1()  asm volatile("cp.async.wait_group 1;" ::: "memory")
#define CP_WAIT0()  asm volatile("cp.async.wait_group 0;" ::: "memory")

__device__ __forceinline__ unsigned long long dkey(float d, int code) {
    uint32_t b = __float_as_uint(d);
    b = (b & 0x80000000u) ? ~b : (b | 0x80000000u);
    return ((unsigned long long)b << 32) | (unsigned)code;
}
__device__ __forceinline__ float key2f(unsigned long long k) {
    uint32_t b = (uint32_t)(k >> 32);
    b = (b & 0x80000000u) ? (b & 0x7FFFFFFFu) : ~b;
    return __uint_as_float(b);
}

// ---------------- prep ----------------
__global__ void prep_split(const float* __restrict__ emb) {
    int i4 = (blockIdx.x * blockDim.x + threadIdx.x) * 4;
    float4 v = *(const float4*)(emb + i4);
    float vv[4] = {v.x, v.y, v.z, v.w};
    __half h[4];
#pragma unroll
    for (int j = 0; j < 4; j++) h[j] = __float2half_rn(vv[j]);
    *(uint2*)(g_Ehi + i4) = *(uint2*)h;
}
__global__ void prep_e2(const float* __restrict__ emb) {
    int k = blockIdx.x * blockDim.x + threadIdx.x;
    if (k < NCODES) {
        const float* row = emb + (size_t)k * KDIM;
        float s = 0.f;
#pragma unroll 8
        for (int i = 0; i < KDIM; i++) s += row[i] * row[i];
        g_e2[k] = s;
    }
}

// ---------------- main ----------------
__global__ __launch_bounds__(256, 1) void vq_mma_kernel(
    const float* __restrict__ z, const float* __restrict__ emb, float* __restrict__ out)
{
    extern __shared__ char sm[];
    const uint32_t sbase = (uint32_t)__cvta_generic_to_shared(sm);

    const int tid  = threadIdx.x;
    const int lane = tid & 31;
    const int wid  = tid >> 5;
    const int wm   = wid >> 2;
    const int wn   = wid & 3;
    const int gr   = lane >> 2;
    const int lc   = lane & 3;

    float* e2s = (float*)(sm + E2_OFF);
    unsigned long long* minkey = (unsigned long long*)(sm + MK_OFF);
    unsigned* cnt = (unsigned*)(sm + CNT_OFF);
    int* lst = (int*)(sm + LST_OFF);

    for (int i = tid; i < NCODES; i += 256) e2s[i] = g_e2[i];
    if (tid < MCTA) { minkey[tid] = ~0ULL; cnt[tid] = 0u; }

    // ---- convert X slice fp32 -> fp16 hi/lo into smem (hi: MMA; lo: rescue)
    const int mbase = blockIdx.x * MCTA;
    const float* zt = z + ((size_t)(mbase >> 12) * KDIM * NPIX) + (mbase & (NPIX - 1));
    {
        const int m = tid & 127;
        const int half = tid >> 7;
        char* arowh = sm + AHI_OFF + (size_t)m * (ASTR * 2);
        char* arowl = sm + ALO_OFF + (size_t)m * (ASTR * 2);
#pragma unroll 4
        for (int j = 0; j < 64; j++) {
            int k0 = half * 128 + j * 2;
            float v0 = zt[(size_t)k0 * NPIX + m];
            float v1 = zt[(size_t)(k0 + 1) * NPIX + m];
            __half h0 = __float2half_rn(v0), h1 = __float2half_rn(v1);
            __half l0 = __float2half_rn(v0 - __half2float(h0));
            __half l1 = __float2half_rn(v1 - __half2float(h1));
            *(uint32_t*)(arowh + k0 * 2) = (uint32_t)__half_as_ushort(h0) | ((uint32_t)__half_as_ushort(h1) << 16);
            *(uint32_t*)(arowl + k0 * 2) = (uint32_t)__half_as_ushort(l0) | ((uint32_t)__half_as_ushort(l1) << 16);
        }
    }
    __syncthreads();

    auto loadB = [&](int nch, int kt, int buf) {
        int k0 = kt * BK;
        uint32_t bb = sbase + (buf ? B1_OFF : B0_OFF);
#pragma unroll
        for (int j = 0; j < 4; j++) {
            int chunk = tid * 4 + j;
            int row = chunk >> 3, ch = chunk & 7;
            const __half* src = g_Ehi + (size_t)(nch * 128 + row) * KDIM + k0 + ch * 8;
            cp16(bb + row * (BSTR * 2) + ch * 16, src);
        }
        CP_COMMIT();
    };

    const uint32_t a_lrow = (lane & 15);
    const uint32_t a_lq   = (lane >> 4) * 16;
    const uint32_t b_lrow = (lane & 7) + ((lane & 16) >> 1);
    const uint32_t b_lq   = ((lane >> 3) & 1) * 16;

    for (int nch = 0; nch < 8; nch++) {
        float c[4][4][4];
#pragma unroll
        for (int mi = 0; mi < 4; mi++)
#pragma unroll
            for (int ni = 0; ni < 4; ni++)
#pragma unroll
                for (int r = 0; r < 4; r++) c[mi][ni][r] = 0.f;

        loadB(nch, 0, 0);

        for (int kt = 0; kt < KT; kt++) {
            if (kt + 1 < KT) { loadB(nch, kt + 1, (kt + 1) & 1); CP_WAIT1(); }
            else             { CP_WAIT0(); }
            __syncthreads();

            const uint32_t akb   = (uint32_t)(kt * BK * 2);
            const uint32_t bbase = sbase + ((kt & 1) ? B1_OFF : B0_OFF);

#pragma unroll
            for (int k16 = 0; k16 < 4; k16++) {
                uint32_t af[4][4];
#pragma unroll
                for (int mi = 0; mi < 4; mi++) {
                    uint32_t addr = sbase + AHI_OFF
                        + (uint32_t)(wm * 64 + mi * 16 + a_lrow) * (ASTR * 2)
                        + akb + (uint32_t)k16 * 32 + a_lq;
                    ldmx4(af[mi], addr);
                }
                uint32_t bf[2][4];
#pragma unroll
                for (int ni2 = 0; ni2 < 2; ni2++) {
                    uint32_t addr = bbase
                        + (uint32_t)(wn * 32 + ni2 * 16 + b_lrow) * (BSTR * 2)
                        + (uint32_t)k16 * 32 + b_lq;
                    ldmx4(bf[ni2], addr);
                }
#pragma unroll
                for (int mi = 0; mi < 4; mi++)
#pragma unroll
                    for (int ni = 0; ni < 4; ni++)
                        mma16816(c[mi][ni], af[mi], bf[ni >> 1][(ni & 1) * 2], bf[ni >> 1][(ni & 1) * 2 + 1]);
            }
            __syncthreads();
        }

        // ---- screening epilogue: running min + candidate append
#pragma unroll
        for (int mi = 0; mi < 4; mi++) {
#pragma unroll
            for (int rh = 0; rh < 2; rh++) {
                int row = wm * 64 + mi * 16 + gr + rh * 8;
                float dv[8]; int cd[8];
                unsigned long long best = ~0ULL;
#pragma unroll
                for (int ni = 0; ni < 4; ni++) {
#pragma unroll
                    for (int cp = 0; cp < 2; cp++) {
                        int idx = ni * 2 + cp;
                        float s = c[mi][ni][rh * 2 + cp];
                        int code = nch * 128 + wn * 32 + ni * 8 + lc * 2 + cp;
                        float d = fmaf(-2.f, s, e2s[code]);
                        dv[idx] = d; cd[idx] = code;
                        unsigned long long key = dkey(d, code);
                        if (key < best) best = key;
                    }
                }
                unsigned long long old = atomicMin(&minkey[row], best);
                unsigned long long cur = old < best ? old : best;  // >= final min: safe
                float thr = key2f(cur) + DELTA;
#pragma unroll
                for (int idx = 0; idx < 8; idx++) {
                    if (dv[idx] <= thr) {
                        unsigned pos = atomicAdd(&cnt[row], 1u);
                        if (pos < LCAP) lst[row * LCAP + pos] = cd[idx];
                    }
                }
            }
        }
        __syncthreads();
    }

    // ---- exact rescore of candidates (warp per pixel)
    for (int row = wid; row < MCTA; row += 8) {
        // reconstruct exact fp32 x for this pixel: lane holds k = lane*8 .. +7
        float xv[8];
        const char* arh = sm + AHI_OFF + (size_t)row * (ASTR * 2);
        const char* arl = sm + ALO_OFF + (size_t)row * (ASTR * 2);
#pragma unroll
        for (int j = 0; j < 8; j++) {
            int k = lane * 8 + j;
            xv[j] = __half2float(*(const __half*)(arh + k * 2))
                  + __half2float(*(const __half*)(arl + k * 2));
        }
        unsigned n = cnt[row];
        unsigned long long best = ~0ULL;
        if (n <= LCAP) {
            for (unsigned i = 0; i < n; i++) {
                int code = lst[row * LCAP + i];
                const float* e = emb + (size_t)code * KDIM;
                float s = 0.f;
#pragma unroll
                for (int j = 0; j < 8; j++) s = fmaf(xv[j], e[lane * 8 + j], s);
#pragma unroll
                for (int off = 16; off > 0; off >>= 1)
                    s += __shfl_xor_sync(0xffffffffu, s, off);
                float d = fmaf(-2.f, s, e2s[code]);
                unsigned long long key = dkey(d, code);
                if (key < best) best = key;
            }
        } else {
            // overflow (rare): exact rescan of all codes
            for (int code = 0; code < NCODES; code++) {
                const float* e = emb + (size_t)code * KDIM;
                float s = 0.f;
#pragma unroll
                for (int j = 0; j < 8; j++) s = fmaf(xv[j], e[lane * 8 + j], s);
#pragma unroll
                for (int off = 16; off > 0; off >>= 1)
                    s += __shfl_xor_sync(0xffffffffu, s, off);
                float d = fmaf(-2.f, s, e2s[code]);
                unsigned long long key = dkey(d, code);
                if (key < best) best = key;
            }
        }
        if (lane == 0)
            out[mbase + row] = (float)(unsigned)(best & 0xFFFFFFFFull);
    }
}

extern "C" void kernel_launch(void* const* d_in, const int* in_sizes, int n_in,
                              void* d_out, int out_size) {
    const float* z;
    const float* emb;
    if (n_in >= 2 && in_sizes[1] > in_sizes[0]) {
        z = (const float*)d_in[1];  emb = (const float*)d_in[0];
    } else {
        z = (const float*)d_in[0];  emb = (const float*)d_in[n_in > 1 ? 1 : 0];
    }
    float* out = (float*)d_out;

    cudaFuncSetAttribute(vq_mma_kernel, cudaFuncAttributeMaxDynamicSharedMemorySize, SMEM_SZ);

    prep_split<<<256, 256>>>(emb);
    prep_e2<<<4, 256>>>(emb);
    vq_mma_kernel<<<65536 / MCTA, 256, SMEM_SZ>>>(z, emb, out);
}

// round 9
// speedup vs baseline: 1.2190x; 1.2190x over previous
#include <cuda_runtime.h>
#include <cuda_fp16.h>
#include <cstdint>

// CodeBook VQ argmin via legacy HMMA (m16n8k16 fp16->fp32), exact fp16-split 3-pass:
//   S = Xhi*Ehi^T + Xlo*Ehi^T + Xhi*Elo^T   (residual ~5e-6 << top-2 gaps)
// R9: 512 threads (16 warps, 4/SMSP), warp tile 32x64, register argmin epilogue.

#define NCODES 1024
#define KDIM   256
#define NPIX   4096
#define MCTA   128

#define ASTR   264              // A row stride in halves (528B), ldmatrix conflict-free
#define BSTR   72               // B row stride in halves (144B)
#define BK     64
#define NTILE  96               // 8 nchunks x 12 ktiles (3 segs x 4)

#define AHI_OFF   0             // 128*528 = 67584
#define ALO_OFF   67584
#define B0_OFF    135168        // 128*144 = 18432
#define B1_OFF    153600
#define E2_OFF    172032        // 4096
#define MK_OFF    176128        // 128*8 = 1024
#define SMEM_SZ   177152

__device__ __align__(16) __half g_Ehi[NCODES * KDIM];
__device__ __align__(16) __half g_Elo[NCODES * KDIM];
__device__ float g_e2[NCODES];

__device__ __forceinline__ void ldmx4(uint32_t* r, uint32_t addr) {
    asm volatile("ldmatrix.sync.aligned.m8n8.x4.shared.b16 {%0,%1,%2,%3}, [%4];"
                 : "=r"(r[0]), "=r"(r[1]), "=r"(r[2]), "=r"(r[3]) : "r"(addr));
}
__device__ __forceinline__ void mma16816(float* c, const uint32_t* a, uint32_t b0, uint32_t b1) {
    asm volatile("mma.sync.aligned.m16n8k16.row.col.f32.f16.f16.f32 "
                 "{%0,%1,%2,%3}, {%4,%5,%6,%7}, {%8,%9}, {%0,%1,%2,%3};"
                 : "+f"(c[0]), "+f"(c[1]), "+f"(c[2]), "+f"(c[3])
                 : "r"(a[0]), "r"(a[1]), "r"(a[2]), "r"(a[3]), "r"(b0), "r"(b1));
}
__device__ __forceinline__ void cp16(uint32_t dst, const void* src) {
    asm volatile("cp.async.cg.shared.global [%0], [%1], 16;"
                 :: "r"(dst), "l"(__cvta_generic_to_global(src)) : "memory");
}
#define CP_COMMIT() asm volatile("cp.async.commit_group;" ::: "memory")
#define CP_WAIT1()  asm volatile("cp.async.wait_group 1;" ::: "memory")
#define CP_WAIT0()  asm volatile("cp.async.wait_group 0;" ::: "memory")

__device__ __forceinline__ unsigned long long dkey(float d, int code) {
    uint32_t b = __float_as_uint(d);
    b = (b & 0x80000000u) ? ~b : (b | 0x80000000u);
    return ((unsigned long long)b << 32) | (unsigned)code;
}

// ---------------- prep ----------------
__global__ void prep_split(const float* __restrict__ emb) {
    int i4 = (blockIdx.x * blockDim.x + threadIdx.x) * 4;
    float4 v = *(const float4*)(emb + i4);
    float vv[4] = {v.x, v.y, v.z, v.w};
    __half h[4], l[4];
#pragma unroll
    for (int j = 0; j < 4; j++) {
        h[j] = __float2half_rn(vv[j]);
        l[j] = __float2half_rn(vv[j] - __half2float(h[j]));
    }
    *(uint2*)(g_Ehi + i4) = *(uint2*)h;
    *(uint2*)(g_Elo + i4) = *(uint2*)l;
}
__global__ void prep_e2(const float* __restrict__ emb) {
    int k = blockIdx.x * blockDim.x + threadIdx.x;
    if (k < NCODES) {
        const float* row = emb + (size_t)k * KDIM;
        float s = 0.f;
#pragma unroll 8
        for (int i = 0; i < KDIM; i++) s += row[i] * row[i];
        g_e2[k] = s;
    }
}

// ---------------- main kernel ----------------
__global__ __launch_bounds__(512, 1) void vq_mma_kernel(
    const float* __restrict__ z, float* __restrict__ out)
{
    extern __shared__ char sm[];
    const uint32_t sbase = (uint32_t)__cvta_generic_to_shared(sm);

    const int tid  = threadIdx.x;
    const int lane = tid & 31;
    const int wid  = tid >> 5;          // 16 warps
    const int wm   = wid >> 1;          // 0..7 : rows wm*16.. (two 16-row slabs via mi)
    const int wn   = wid & 1;           // 0..1 : cols wn*64..
    const int gr   = lane >> 2;
    const int lc   = lane & 3;

    float* e2s = (float*)(sm + E2_OFF);
    unsigned long long* minkey = (unsigned long long*)(sm + MK_OFF);

    for (int i = tid; i < NCODES; i += 512) e2s[i] = g_e2[i];
    if (tid < MCTA) minkey[tid] = ~0ULL;

    // ---- convert X slice fp32 -> fp16 hi/lo into smem A ([m][k], stride ASTR)
    const int mbase = blockIdx.x * MCTA;
    const float* zt = z + ((size_t)(mbase >> 12) * KDIM * NPIX) + (mbase & (NPIX - 1));
    {
        const int m = tid & 127;
        const int q = tid >> 7;                    // 0..3 -> k range [q*64, q*64+64)
        char* arowh = sm + AHI_OFF + (size_t)m * (ASTR * 2);
        char* arowl = sm + ALO_OFF + (size_t)m * (ASTR * 2);
#pragma unroll 4
        for (int j = 0; j < 32; j++) {
            int k0 = q * 64 + j * 2;
            float v0 = zt[(size_t)k0 * NPIX + m];
            float v1 = zt[(size_t)(k0 + 1) * NPIX + m];
            __half h0 = __float2half_rn(v0), h1 = __float2half_rn(v1);
            __half l0 = __float2half_rn(v0 - __half2float(h0));
            __half l1 = __float2half_rn(v1 - __half2float(h1));
            *(uint32_t*)(arowh + k0 * 2) = (uint32_t)__half_as_ushort(h0) | ((uint32_t)__half_as_ushort(h1) << 16);
            *(uint32_t*)(arowl + k0 * 2) = (uint32_t)__half_as_ushort(l0) | ((uint32_t)__half_as_ushort(l1) << 16);
        }
    }
    __syncthreads();

    // B tile loader: tile g -> nch = g/12, kt = g%12 (seg = kt>>2, k0 = (kt&3)*64)
    auto loadB = [&](int g) {
        int nch = (g * 43) >> 9;                   // g/12 for g<96 (43/512 trick) 
        int kt  = g - nch * 12;
        int seg = kt >> 2;
        int k0  = (kt & 3) * BK;
        const __half* esrc = (seg == 2 ? g_Elo : g_Ehi);
        uint32_t bb = sbase + ((g & 1) ? B1_OFF : B0_OFF);
#pragma unroll
        for (int j = 0; j < 2; j++) {
            int chunk = tid * 2 + j;               // 0..1023
            int row = chunk >> 3, ch = chunk & 7;
            const __half* src = esrc + (size_t)(nch * 128 + row) * KDIM + k0 + ch * 8;
            cp16(bb + row * (BSTR * 2) + ch * 16, src);
        }
        CP_COMMIT();
    };

    const uint32_t a_lrow = (lane & 15);
    const uint32_t a_lq   = (lane >> 4) * 16;
    const uint32_t b_lrow = (lane & 7) + ((lane & 16) >> 1);
    const uint32_t b_lq   = ((lane >> 3) & 1) * 16;

    unsigned long long best[2][2];                 // [mi][rh] rows: wm*16+mi*... see below
    // rows covered by this thread: r(mi,rh) = (wm&3)*32 + mi*16 + gr + rh*8 ... define below
#pragma unroll
    for (int i = 0; i < 2; i++)
#pragma unroll
        for (int j = 0; j < 2; j++) best[i][j] = ~0ULL;

    // warp row origin: 4 row-groups of 32 (wm>>1 isn't needed: wm 0..7 / wn split)
    const int wrow = (wid >> 1) * 16;              // 8 slabs of 16 rows -> mi covers +0 only
    // NOTE: with 16 warps as 8x2 grid, warp tile is 16 rows x 64 cols, mi loop = 1.
    // Redefine: mi dimension unused (1), ni = 8.

    float c[8][4];                                 // 8 n-frags x 4

    loadB(0);

    for (int g = 0; g < NTILE; g++) {
        const int kt  = g - ((g * 43) >> 9) * 12;

        if (kt == 0) {
#pragma unroll
            for (int ni = 0; ni < 8; ni++)
#pragma unroll
                for (int r = 0; r < 4; r++) c[ni][r] = 0.f;
        }

        if (g + 1 < NTILE) { loadB(g + 1); CP_WAIT1(); }
        else               { CP_WAIT0(); }
        __syncthreads();

        const int seg = kt >> 2;
        const uint32_t abase = sbase + (seg == 1 ? ALO_OFF : AHI_OFF);
        const uint32_t akb   = (uint32_t)((kt & 3) * BK * 2);
        const uint32_t bbase = sbase + ((g & 1) ? B1_OFF : B0_OFF);

#pragma unroll
        for (int k16 = 0; k16 < 4; k16++) {
            uint32_t af[4];
            {
                uint32_t addr = abase
                    + (uint32_t)(wrow + a_lrow) * (ASTR * 2)
                    + akb + (uint32_t)k16 * 32 + a_lq;
                ldmx4(af, addr);
            }
            uint32_t bf[4][4];
#pragma unroll
            for (int ni2 = 0; ni2 < 4; ni2++) {
                uint32_t addr = bbase
                    + (uint32_t)(wn * 64 + ni2 * 16 + b_lrow) * (BSTR * 2)
                    + (uint32_t)k16 * 32 + b_lq;
                ldmx4(bf[ni2], addr);
            }
#pragma unroll
            for (int ni = 0; ni < 8; ni++)
                mma16816(c[ni], af, bf[ni >> 1][(ni & 1) * 2], bf[ni >> 1][(ni & 1) * 2 + 1]);
        }
        __syncthreads();

        if (kt == 11) {
            const int nch = ((g * 43) >> 9);
#pragma unroll
            for (int ni = 0; ni < 8; ni++) {
#pragma unroll
                for (int rh = 0; rh < 2; rh++) {
#pragma unroll
                    for (int cp = 0; cp < 2; cp++) {
                        float s = c[ni][rh * 2 + cp];
                        int code = nch * 128 + wn * 64 + ni * 8 + lc * 2 + cp;
                        float d = fmaf(-2.f, s, e2s[code]);
                        unsigned long long key = dkey(d, code);
                        if (key < best[0][rh]) best[0][rh] = key;
                    }
                }
            }
        }
    }

    // ---- final argmin merge: one atomicMin per (thread, row-half)
#pragma unroll
    for (int rh = 0; rh < 2; rh++) {
        int row = wrow + gr + rh * 8;
        atomicMin(&minkey[row], best[0][rh]);
    }
    __syncthreads();

    if (tid < MCTA)
        out[mbase + tid] = (float)(unsigned)(minkey[tid] & 0xFFFFFFFFull);
}

extern "C" void kernel_launch(void* const* d_in, const int* in_sizes, int n_in,
                              void* d_out, int out_size) {
    const float* z;
    const float* emb;
    if (n_in >= 2 && in_sizes[1] > in_sizes[0]) {
        z = (const float*)d_in[1];  emb = (const float*)d_in[0];
    } else {
        z = (const float*)d_in[0];  emb = (const float*)d_in[n_in > 1 ? 1 : 0];
    }
    float* out = (float*)d_out;

    cudaFuncSetAttribute(vq_mma_kernel, cudaFuncAttributeMaxDynamicSharedMemorySize, SMEM_SZ);

    prep_split<<<256, 256>>>(emb);
    prep_e2<<<4, 256>>>(emb);
    vq_mma_kernel<<<65536 / MCTA, 512, SMEM_SZ>>>(z, out);
}

// round 10
// speedup vs baseline: 1.5465x; 1.2687x over previous
#include <cuda_runtime.h>
#include <cuda_fp16.h>
#include <cstdint>

// CodeBook VQ argmin: one-pass fp16 HMMA screen + exact fp32 candidate rescue.
//   d_hi[k] = e2[k] - 2*(Xhi·Ehi^T)  (err std ~1.6e-2; Δ=0.5 = 2x15σ safety)
//   candidates: d_hi <= running_min + Δ  (running_min >= final min => no miss)
//   rescue: exact fp32 dot with ORIGINAL z and emb, tie -> lowest code.

#define NCODES 1024
#define KDIM   256
#define NPIX   4096
#define MCTA   128
#define DELTA  0.5f
#define LCAP   16

#define ASTR   264              // A row stride halves (528B)
#define BSTR   72               // B row stride halves (144B)
#define BK     64
#define NTILE  32               // 8 nchunks x 4 ktiles
#define DMSTR  136              // dmat row stride floats (544B)

#define AHI_OFF   0             // 128*528 = 67584
#define B0_OFF    67584         // 18432
#define B1_OFF    86016         // 18432
#define DM_OFF    104448        // 128*544 = 69632
#define E2_OFF    174080        // 4096
#define LST_OFF   178176        // 128*16*4 = 8192
#define SMEM_SZ   186368

__device__ __align__(16) __half g_Ehi[NCODES * KDIM];
__device__ float g_e2[NCODES];

__device__ __forceinline__ void ldmx4(uint32_t* r, uint32_t addr) {
    asm volatile("ldmatrix.sync.aligned.m8n8.x4.shared.b16 {%0,%1,%2,%3}, [%4];"
                 : "=r"(r[0]), "=r"(r[1]), "=r"(r[2]), "=r"(r[3]) : "r"(addr));
}
__device__ __forceinline__ void mma16816(float* c, const uint32_t* a, uint32_t b0, uint32_t b1) {
    asm volatile("mma.sync.aligned.m16n8k16.row.col.f32.f16.f16.f32 "
                 "{%0,%1,%2,%3}, {%4,%5,%6,%7}, {%8,%9}, {%0,%1,%2,%3};"
                 : "+f"(c[0]), "+f"(c[1]), "+f"(c[2]), "+f"(c[3])
                 : "r"(a[0]), "r"(a[1]), "r"(a[2]), "r"(a[3]), "r"(b0), "r"(b1));
}
__device__ __forceinline__ void cp16(uint32_t dst, const void* src) {
    asm volatile("cp.async.cg.shared.global [%0], [%1], 16;"
                 :: "r"(dst), "l"(__cvta_generic_to_global(src)) : "memory");
}
#define CP_COMMIT() asm volatile("cp.async.commit_group;" ::: "memory")
#define CP_WAIT1()  asm volatile("cp.async.wait_group 1;" ::: "memory")
#define CP_WAIT0()  asm volatile("cp.async.wait_group 0;" ::: "memory")

__device__ __forceinline__ unsigned long long dkey(float d, int code) {
    uint32_t b = __float_as_uint(d);
    b = (b & 0x80000000u) ? ~b : (b | 0x80000000u);
    return ((unsigned long long)b << 32) | (unsigned)code;
}
__device__ __forceinline__ float key2f(unsigned long long k) {
    uint32_t b = (uint32_t)(k >> 32);
    b = (b & 0x80000000u) ? (b & 0x7FFFFFFFu) : ~b;
    return __uint_as_float(b);
}

// ---------------- prep ----------------
__global__ void prep_split(const float* __restrict__ emb) {
    int i4 = (blockIdx.x * blockDim.x + threadIdx.x) * 4;
    float4 v = *(const float4*)(emb + i4);
    float vv[4] = {v.x, v.y, v.z, v.w};
    __half h[4];
#pragma unroll
    for (int j = 0; j < 4; j++) h[j] = __float2half_rn(vv[j]);
    *(uint2*)(g_Ehi + i4) = *(uint2*)h;
}
__global__ void prep_e2(const float* __restrict__ emb) {
    int k = blockIdx.x * blockDim.x + threadIdx.x;
    if (k < NCODES) {
        const float* row = emb + (size_t)k * KDIM;
        float s = 0.f;
#pragma unroll 8
        for (int i = 0; i < KDIM; i++) s += row[i] * row[i];
        g_e2[k] = s;
    }
}

// ---------------- main ----------------
__global__ __launch_bounds__(512, 1) void vq_mma_kernel(
    const float* __restrict__ z, const float* __restrict__ emb, float* __restrict__ out)
{
    extern __shared__ char sm[];
    const uint32_t sbase = (uint32_t)__cvta_generic_to_shared(sm);

    const int tid  = threadIdx.x;
    const int lane = tid & 31;
    const int wid  = tid >> 5;              // 16 warps
    const int wn   = wid & 1;
    const int wrow = (wid >> 1) * 16;       // 16-row slab
    const int gr   = lane >> 2;
    const int lc   = lane & 3;

    float* e2s = (float*)(sm + E2_OFF);
    float* dmat = (float*)(sm + DM_OFF);
    int* lst = (int*)(sm + LST_OFF);

    for (int i = tid; i < NCODES; i += 512) e2s[i] = g_e2[i];

    // ---- convert X slice fp32 -> fp16 hi into smem A ([m][k], stride ASTR)
    const int mbase = blockIdx.x * MCTA;
    const float* zt = z + ((size_t)(mbase >> 12) * KDIM * NPIX) + (mbase & (NPIX - 1));
    {
        const int m = tid & 127;
        const int q = tid >> 7;             // k range [q*64, q*64+64)
        char* arowh = sm + AHI_OFF + (size_t)m * (ASTR * 2);
#pragma unroll 4
        for (int j = 0; j < 32; j++) {
            int k0 = q * 64 + j * 2;
            float v0 = zt[(size_t)k0 * NPIX + m];
            float v1 = zt[(size_t)(k0 + 1) * NPIX + m];
            __half h0 = __float2half_rn(v0), h1 = __float2half_rn(v1);
            *(uint32_t*)(arowh + k0 * 2) =
                (uint32_t)__half_as_ushort(h0) | ((uint32_t)__half_as_ushort(h1) << 16);
        }
    }
    __syncthreads();

    auto loadB = [&](int g) {
        int nch = g >> 2, kt = g & 3;
        uint32_t bb = sbase + ((g & 1) ? B1_OFF : B0_OFF);
#pragma unroll
        for (int j = 0; j < 2; j++) {
            int chunk = tid * 2 + j;        // 0..1023
            int row = chunk >> 3, ch = chunk & 7;
            const __half* src = g_Ehi + (size_t)(nch * 128 + row) * KDIM + kt * BK + ch * 8;
            cp16(bb + row * (BSTR * 2) + ch * 16, src);
        }
        CP_COMMIT();
    };

    const uint32_t a_lrow = (lane & 15);
    const uint32_t a_lq   = (lane >> 4) * 16;
    const uint32_t b_lrow = (lane & 7) + ((lane & 16) >> 1);
    const uint32_t b_lq   = ((lane >> 3) & 1) * 16;

    // owner-warp state: warp wid owns pixels wid*8 .. wid*8+7
    unsigned long long runmin[8];
    unsigned cntreg[8];
#pragma unroll
    for (int i = 0; i < 8; i++) { runmin[i] = ~0ULL; cntreg[i] = 0u; }

    float c[8][4];
    loadB(0);

    for (int g = 0; g < NTILE; g++) {
        const int kt = g & 3, nch = g >> 2;
        if (kt == 0) {
#pragma unroll
            for (int ni = 0; ni < 8; ni++)
#pragma unroll
                for (int r = 0; r < 4; r++) c[ni][r] = 0.f;
        }

        if (g + 1 < NTILE) { loadB(g + 1); CP_WAIT1(); }
        else               { CP_WAIT0(); }
        __syncthreads();

        const uint32_t akb   = (uint32_t)(kt * BK * 2);
        const uint32_t bbase = sbase + ((g & 1) ? B1_OFF : B0_OFF);

#pragma unroll
        for (int k16 = 0; k16 < 4; k16++) {
            uint32_t af[4];
            ldmx4(af, sbase + AHI_OFF + (uint32_t)(wrow + a_lrow) * (ASTR * 2)
                      + akb + (uint32_t)k16 * 32 + a_lq);
            uint32_t bf[4][4];
#pragma unroll
            for (int ni2 = 0; ni2 < 4; ni2++)
                ldmx4(bf[ni2], bbase + (uint32_t)(wn * 64 + ni2 * 16 + b_lrow) * (BSTR * 2)
                               + (uint32_t)k16 * 32 + b_lq);
#pragma unroll
            for (int ni = 0; ni < 8; ni++)
                mma16816(c[ni], af, bf[ni >> 1][(ni & 1) * 2], bf[ni >> 1][(ni & 1) * 2 + 1]);
        }
        __syncthreads();

        if (kt == 3) {
            // ---- store d_hi to dmat
#pragma unroll
            for (int ni = 0; ni < 8; ni++) {
#pragma unroll
                for (int rh = 0; rh < 2; rh++) {
                    int row = wrow + gr + rh * 8;
                    int col = wn * 64 + ni * 8 + lc * 2;
                    float d0 = fmaf(-2.f, c[ni][rh * 2 + 0], e2s[nch * 128 + col]);
                    float d1 = fmaf(-2.f, c[ni][rh * 2 + 1], e2s[nch * 128 + col + 1]);
                    *(float2*)(&dmat[row * DMSTR + col]) = make_float2(d0, d1);
                }
            }
            __syncthreads();

            // ---- screen: warp owns 8 pixels, lane handles 4 codes
#pragma unroll 1
            for (int pi = 0; pi < 8; pi++) {
                int p = wid * 8 + pi;
                float4 v = *(const float4*)(&dmat[p * DMSTR + lane * 4]);
                float dv[4] = {v.x, v.y, v.z, v.w};
                unsigned long long kmin = ~0ULL;
#pragma unroll
                for (int j = 0; j < 4; j++) {
                    unsigned long long k = dkey(dv[j], nch * 128 + lane * 4 + j);
                    if (k < kmin) kmin = k;
                }
#pragma unroll
                for (int off = 16; off > 0; off >>= 1) {
                    unsigned long long o = __shfl_xor_sync(0xffffffffu, kmin, off);
                    if (o < kmin) kmin = o;
                }
                if (kmin < runmin[pi]) runmin[pi] = kmin;
                float thr = key2f(runmin[pi]) + DELTA;
#pragma unroll
                for (int j = 0; j < 4; j++) {
                    bool pred = (dv[j] <= thr);
                    unsigned mask = __ballot_sync(0xffffffffu, pred);
                    if (pred) {
                        unsigned pos = cntreg[pi] + __popc(mask & ((1u << lane) - 1u));
                        if (pos < LCAP)
                            lst[p * LCAP + pos] = nch * 128 + lane * 4 + j;
                    }
                    cntreg[pi] += __popc(mask);
                }
            }
            __syncthreads();
        }
    }

    // ---- exact fp32 rescue: owner warp, original z and emb
#pragma unroll 1
    for (int pi = 0; pi < 8; pi++) {
        int p = wid * 8 + pi;
        float xv[8];
#pragma unroll
        for (int j = 0; j < 8; j++)
            xv[j] = zt[(size_t)(lane * 8 + j) * NPIX + p];

        unsigned long long best = ~0ULL;
        unsigned n = cntreg[pi];
        if (n <= LCAP) {
            for (unsigned i = 0; i < n; i++) {
                int code = lst[p * LCAP + i];
                const float* e = emb + (size_t)code * KDIM + lane * 8;
                float4 e0 = *(const float4*)(e);
                float4 e1 = *(const float4*)(e + 4);
                float s = xv[0] * e0.x;
                s = fmaf(xv[1], e0.y, s); s = fmaf(xv[2], e0.z, s); s = fmaf(xv[3], e0.w, s);
                s = fmaf(xv[4], e1.x, s); s = fmaf(xv[5], e1.y, s);
                s = fmaf(xv[6], e1.z, s); s = fmaf(xv[7], e1.w, s);
#pragma unroll
                for (int off = 16; off > 0; off >>= 1)
                    s += __shfl_xor_sync(0xffffffffu, s, off);
                unsigned long long key = dkey(fmaf(-2.f, s, e2s[code]), code);
                if (key < best) best = key;
            }
        } else {
            for (int code = 0; code < NCODES; code++) {
                const float* e = emb + (size_t)code * KDIM + lane * 8;
                float4 e0 = *(const float4*)(e);
                float4 e1 = *(const float4*)(e + 4);
                float s = xv[0] * e0.x;
                s = fmaf(xv[1], e0.y, s); s = fmaf(xv[2], e0.z, s); s = fmaf(xv[3], e0.w, s);
                s = fmaf(xv[4], e1.x, s); s = fmaf(xv[5], e1.y, s);
                s = fmaf(xv[6], e1.z, s); s = fmaf(xv[7], e1.w, s);
#pragma unroll
                for (int off = 16; off > 0; off >>= 1)
                    s += __shfl_xor_sync(0xffffffffu, s, off);
                unsigned long long key = dkey(fmaf(-2.f, s, e2s[code]), code);
                if (key < best) best = key;
            }
        }
        if (lane == 0)
            out[mbase + p] = (float)(unsigned)(best & 0xFFFFFFFFull);
    }
}

extern "C" void kernel_launch(void* const* d_in, const int* in_sizes, int n_in,
                              void* d_out, int out_size) {
    const float* z;
    const float* emb;
    if (n_in >= 2 && in_sizes[1] > in_sizes[0]) {
        z = (const float*)d_in[1];  emb = (const float*)d_in[0];
    } else {
        z = (const float*)d_in[0];  emb = (const float*)d_in[n_in > 1 ? 1 : 0];
    }
    float* out = (float*)d_out;

    cudaFuncSetAttribute(vq_mma_kernel, cudaFuncAttributeMaxDynamicSharedMemorySize, SMEM_SZ);

    prep_split<<<256, 256>>>(emb);
    prep_e2<<<4, 256>>>(emb);
    vq_mma_kernel<<<65536 / MCTA, 512, SMEM_SZ>>>(z, emb, out);
}

// round 11
// speedup vs baseline: 2.0904x; 1.3517x over previous
#include <cuda_runtime.h>
#include <cuda_fp16.h>
#include <cstdint>

// CodeBook VQ argmin: one-pass fp16 HMMA screen (register epilogue) + exact rescue.
//   d_hi[k] = e2[k] - 2*(Xhi·Ehi^T);  candidates: d_hi <= running_min + DELTA
//   (running_min >= final min and DELTA >= 2*max|err| => argmin never missed)
//   rescue: exact dot with x~ = fp32(xhi)+fp32(xlo) (err 2^-22) vs fp32 emb.

#define NCODES 1024
#define KDIM   256
#define NPIX   4096
#define MCTA   128
#define DELTA  0.5f
#define LCAP   16

#define ASTR   264              // A row stride halves (528B)
#define BSTR   72               // B row stride halves (144B)
#define BK     64
#define NTILE  32               // 8 nchunks x 4 ktiles

#define AHI_OFF   0             // 128*528 = 67584
#define ALO_OFF   67584         // 67584
#define B0_OFF    135168        // 18432
#define B1_OFF    153600        // 18432
#define E2_OFF    172032        // 4096
#define MK_OFF    176128        // 128*8 = 1024
#define CNT_OFF   177152        // 128*4 = 512
#define LST_OFF   177664        // 128*16*4 = 8192
#define SMEM_SZ   185856

__device__ __align__(16) __half g_Ehi[NCODES * KDIM];
__device__ float g_e2[NCODES];

__device__ __forceinline__ void ldmx4(uint32_t* r, uint32_t addr) {
    asm volatile("ldmatrix.sync.aligned.m8n8.x4.shared.b16 {%0,%1,%2,%3}, [%4];"
                 : "=r"(r[0]), "=r"(r[1]), "=r"(r[2]), "=r"(r[3]) : "r"(addr));
}
__device__ __forceinline__ void mma16816(float* c, const uint32_t* a, uint32_t b0, uint32_t b1) {
    asm volatile("mma.sync.aligned.m16n8k16.row.col.f32.f16.f16.f32 "
                 "{%0,%1,%2,%3}, {%4,%5,%6,%7}, {%8,%9}, {%0,%1,%2,%3};"
                 : "+f"(c[0]), "+f"(c[1]), "+f"(c[2]), "+f"(c[3])
                 : "r"(a[0]), "r"(a[1]), "r"(a[2]), "r"(a[3]), "r"(b0), "r"(b1));
}
__device__ __forceinline__ void cp16(uint32_t dst, const void* src) {
    asm volatile("cp.async.cg.shared.global [%0], [%1], 16;"
                 :: "r"(dst), "l"(__cvta_generic_to_global(src)) : "memory");
}
#define CP_COMMIT() asm volatile("cp.async.commit_group;" ::: "memory")
#define CP_WAIT1()  asm volatile("cp.async.wait_group 1;" ::: "memory")
#define CP_WAIT0()  asm volatile("cp.async.wait_group 0;" ::: "memory")

__device__ __forceinline__ unsigned long long dkey(float d, int code) {
    uint32_t b = __float_as_uint(d);
    b = (b & 0x80000000u) ? ~b : (b | 0x80000000u);
    return ((unsigned long long)b << 32) | (unsigned)code;
}
__device__ __forceinline__ float key2f(unsigned long long k) {
    uint32_t b = (uint32_t)(k >> 32);
    b = (b & 0x80000000u) ? (b & 0x7FFFFFFFu) : ~b;
    return __uint_as_float(b);
}

// ---------------- prep ----------------
__global__ void prep_split(const float* __restrict__ emb) {
    int i4 = (blockIdx.x * blockDim.x + threadIdx.x) * 4;
    float4 v = *(const float4*)(emb + i4);
    float vv[4] = {v.x, v.y, v.z, v.w};
    __half h[4];
#pragma unroll
    for (int j = 0; j < 4; j++) h[j] = __float2half_rn(vv[j]);
    *(uint2*)(g_Ehi + i4) = *(uint2*)h;
}
__global__ void prep_e2(const float* __restrict__ emb) {
    int k = blockIdx.x * blockDim.x + threadIdx.x;
    if (k < NCODES) {
        const float* row = emb + (size_t)k * KDIM;
        float s = 0.f;
#pragma unroll 8
        for (int i = 0; i < KDIM; i++) s += row[i] * row[i];
        g_e2[k] = s;
    }
}

// ---------------- main ----------------
__global__ __launch_bounds__(512, 1) void vq_mma_kernel(
    const float* __restrict__ z, const float* __restrict__ emb, float* __restrict__ out)
{
    extern __shared__ char sm[];
    const uint32_t sbase = (uint32_t)__cvta_generic_to_shared(sm);

    const int tid  = threadIdx.x;
    const int lane = tid & 31;
    const int wid  = tid >> 5;              // 16 warps
    const int wn   = wid & 1;
    const int wrow = (wid >> 1) * 16;       // 16-row slab
    const int gr   = lane >> 2;
    const int lc   = lane & 3;

    float* e2s = (float*)(sm + E2_OFF);
    unsigned long long* minkey = (unsigned long long*)(sm + MK_OFF);
    unsigned* cnt = (unsigned*)(sm + CNT_OFF);
    int* lst = (int*)(sm + LST_OFF);

    for (int i = tid; i < NCODES; i += 512) e2s[i] = g_e2[i];
    if (tid < MCTA) { minkey[tid] = ~0ULL; cnt[tid] = 0u; }

    // ---- convert X slice fp32 -> fp16 hi/lo into smem ([m][k], stride ASTR)
    const int mbase = blockIdx.x * MCTA;
    const float* zt = z + ((size_t)(mbase >> 12) * KDIM * NPIX) + (mbase & (NPIX - 1));
    {
        const int m = tid & 127;
        const int q = tid >> 7;             // k range [q*64, q*64+64)
        char* arowh = sm + AHI_OFF + (size_t)m * (ASTR * 2);
        char* arowl = sm + ALO_OFF + (size_t)m * (ASTR * 2);
#pragma unroll 4
        for (int j = 0; j < 32; j++) {
            int k0 = q * 64 + j * 2;
            float v0 = zt[(size_t)k0 * NPIX + m];
            float v1 = zt[(size_t)(k0 + 1) * NPIX + m];
            __half h0 = __float2half_rn(v0), h1 = __float2half_rn(v1);
            __half l0 = __float2half_rn(v0 - __half2float(h0));
            __half l1 = __float2half_rn(v1 - __half2float(h1));
            *(uint32_t*)(arowh + k0 * 2) =
                (uint32_t)__half_as_ushort(h0) | ((uint32_t)__half_as_ushort(h1) << 16);
            *(uint32_t*)(arowl + k0 * 2) =
                (uint32_t)__half_as_ushort(l0) | ((uint32_t)__half_as_ushort(l1) << 16);
        }
    }
    __syncthreads();

    auto loadB = [&](int g) {
        int nch = g >> 2, kt = g & 3;
        uint32_t bb = sbase + ((g & 1) ? B1_OFF : B0_OFF);
#pragma unroll
        for (int j = 0; j < 2; j++) {
            int chunk = tid * 2 + j;        // 0..1023
            int row = chunk >> 3, ch = chunk & 7;
            const __half* src = g_Ehi + (size_t)(nch * 128 + row) * KDIM + kt * BK + ch * 8;
            cp16(bb + row * (BSTR * 2) + ch * 16, src);
        }
        CP_COMMIT();
    };

    const uint32_t a_lrow = (lane & 15);
    const uint32_t a_lq   = (lane >> 4) * 16;
    const uint32_t b_lrow = (lane & 7) + ((lane & 16) >> 1);
    const uint32_t b_lq   = ((lane >> 3) & 1) * 16;

    float c[8][4];
    loadB(0);

    for (int g = 0; g < NTILE; g++) {
        const int kt = g & 3, nch = g >> 2;
        if (kt == 0) {
#pragma unroll
            for (int ni = 0; ni < 8; ni++)
#pragma unroll
                for (int r = 0; r < 4; r++) c[ni][r] = 0.f;
        }

        if (g + 1 < NTILE) { loadB(g + 1); CP_WAIT1(); }
        else               { CP_WAIT0(); }
        __syncthreads();

        const uint32_t akb   = (uint32_t)(kt * BK * 2);
        const uint32_t bbase = sbase + ((g & 1) ? B1_OFF : B0_OFF);

#pragma unroll
        for (int k16 = 0; k16 < 4; k16++) {
            uint32_t af[4];
            ldmx4(af, sbase + AHI_OFF + (uint32_t)(wrow + a_lrow) * (ASTR * 2)
                      + akb + (uint32_t)k16 * 32 + a_lq);
            uint32_t bf[4][4];
#pragma unroll
            for (int ni2 = 0; ni2 < 4; ni2++)
                ldmx4(bf[ni2], bbase + (uint32_t)(wn * 64 + ni2 * 16 + b_lrow) * (BSTR * 2)
                               + (uint32_t)k16 * 32 + b_lq);
#pragma unroll
            for (int ni = 0; ni < 8; ni++)
                mma16816(c[ni], af, bf[ni >> 1][(ni & 1) * 2], bf[ni >> 1][(ni & 1) * 2 + 1]);
        }
        __syncthreads();

        if (kt == 3) {
            // ---- phase 1: per-row min from registers, lc-lane reduce, one atomicMin
            unsigned long long kminr[2] = {~0ULL, ~0ULL};
#pragma unroll
            for (int ni = 0; ni < 8; ni++) {
#pragma unroll
                for (int cp = 0; cp < 2; cp++) {
                    int code = nch * 128 + wn * 64 + ni * 8 + lc * 2 + cp;
                    float e2v = e2s[code];
#pragma unroll
                    for (int rh = 0; rh < 2; rh++) {
                        unsigned long long k = dkey(fmaf(-2.f, c[ni][rh * 2 + cp], e2v), code);
                        if (k < kminr[rh]) kminr[rh] = k;
                    }
                }
            }
#pragma unroll
            for (int off = 1; off <= 2; off <<= 1) {
#pragma unroll
                for (int rh = 0; rh < 2; rh++) {
                    unsigned long long o = __shfl_xor_sync(0xffffffffu, kminr[rh], off);
                    if (o < kminr[rh]) kminr[rh] = o;
                }
            }
            if (lc == 0) {
                atomicMin(&minkey[wrow + gr], kminr[0]);
                atomicMin(&minkey[wrow + gr + 8], kminr[1]);
            }
            __syncthreads();

            // ---- phase 2: append candidates (rare) against tightened threshold
            float thr0 = key2f(minkey[wrow + gr]) + DELTA;
            float thr1 = key2f(minkey[wrow + gr + 8]) + DELTA;
#pragma unroll
            for (int ni = 0; ni < 8; ni++) {
#pragma unroll
                for (int cp = 0; cp < 2; cp++) {
                    int code = nch * 128 + wn * 64 + ni * 8 + lc * 2 + cp;
                    float e2v = e2s[code];
                    float d0 = fmaf(-2.f, c[ni][cp], e2v);
                    float d1 = fmaf(-2.f, c[ni][2 + cp], e2v);
                    if (d0 <= thr0) {
                        unsigned pos = atomicAdd(&cnt[wrow + gr], 1u);
                        if (pos < LCAP) lst[(wrow + gr) * LCAP + pos] = code;
                    }
                    if (d1 <= thr1) {
                        unsigned pos = atomicAdd(&cnt[wrow + gr + 8], 1u);
                        if (pos < LCAP) lst[(wrow + gr + 8) * LCAP + pos] = code;
                    }
                }
            }
            __syncthreads();
        }
    }

    // ---- exact rescue: warp owns pixels wid*8..wid*8+7, x~ from smem hi+lo
#pragma unroll 1
    for (int pi = 0; pi < 8; pi++) {
        int p = wid * 8 + pi;
        // lane holds k = lane*8 .. lane*8+7 : one LDS.128 each from hi and lo
        uint4 rh4 = *(const uint4*)(sm + AHI_OFF + (size_t)p * (ASTR * 2) + lane * 16);
        uint4 rl4 = *(const uint4*)(sm + ALO_OFF + (size_t)p * (ASTR * 2) + lane * 16);
        float xv[8];
        {
            const uint32_t hw[4] = {rh4.x, rh4.y, rh4.z, rh4.w};
            const uint32_t lw[4] = {rl4.x, rl4.y, rl4.z, rl4.w};
#pragma unroll
            for (int q = 0; q < 4; q++) {
                __half2 h2 = *(const __half2*)&hw[q];
                __half2 l2 = *(const __half2*)&lw[q];
                float2 hf = __half22float2(h2), lf = __half22float2(l2);
                xv[q * 2 + 0] = hf.x + lf.x;
                xv[q * 2 + 1] = hf.y + lf.y;
            }
        }
        unsigned n = cnt[p];
        unsigned long long best = ~0ULL;
        if (n <= LCAP) {
            for (unsigned i = 0; i < n; i++) {
                int code = lst[p * LCAP + i];
                const float* e = emb + (size_t)code * KDIM + lane * 8;
                float4 e0 = *(const float4*)(e);
                float4 e1 = *(const float4*)(e + 4);
                float s = xv[0] * e0.x;
                s = fmaf(xv[1], e0.y, s); s = fmaf(xv[2], e0.z, s); s = fmaf(xv[3], e0.w, s);
                s = fmaf(xv[4], e1.x, s); s = fmaf(xv[5], e1.y, s);
                s = fmaf(xv[6], e1.z, s); s = fmaf(xv[7], e1.w, s);
#pragma unroll
                for (int off = 16; off > 0; off >>= 1)
                    s += __shfl_xor_sync(0xffffffffu, s, off);
                unsigned long long key = dkey(fmaf(-2.f, s, e2s[code]), code);
                if (key < best) best = key;
            }
        } else {
            for (int code = 0; code < NCODES; code++) {
                const float* e = emb + (size_t)code * KDIM + lane * 8;
                float4 e0 = *(const float4*)(e);
                float4 e1 = *(const float4*)(e + 4);
                float s = xv[0] * e0.x;
                s = fmaf(xv[1], e0.y, s); s = fmaf(xv[2], e0.z, s); s = fmaf(xv[3], e0.w, s);
                s = fmaf(xv[4], e1.x, s); s = fmaf(xv[5], e1.y, s);
                s = fmaf(xv[6], e1.z, s); s = fmaf(xv[7], e1.w, s);
#pragma unroll
                for (int off = 16; off > 0; off >>= 1)
                    s += __shfl_xor_sync(0xffffffffu, s, off);
                unsigned long long key = dkey(fmaf(-2.f, s, e2s[code]), code);
                if (key < best) best = key;
            }
        }
        if (lane == 0)
            out[mbase + p] = (float)(unsigned)(best & 0xFFFFFFFFull);
    }
}

extern "C" void kernel_launch(void* const* d_in, const int* in_sizes, int n_in,
                              void* d_out, int out_size) {
    const float* z;
    const float* emb;
    if (n_in >= 2 && in_sizes[1] > in_sizes[0]) {
        z = (const float*)d_in[1];  emb = (const float*)d_in[0];
    } else {
        z = (const float*)d_in[0];  emb = (const float*)d_in[n_in > 1 ? 1 : 0];
    }
    float* out = (float*)d_out;

    cudaFuncSetAttribute(vq_mma_kernel, cudaFuncAttributeMaxDynamicSharedMemorySize, SMEM_SZ);

    prep_split<<<256, 256>>>(emb);
    prep_e2<<<4, 256>>>(emb);
    vq_mma_kernel<<<65536 / MCTA, 512, SMEM_SZ>>>(z, emb, out);
}